// round 1
// baseline (speedup 1.0000x reference)
#include <cuda_runtime.h>
#include <math.h>

// Problem constants
#define BN 8
#define CC 128
#define HH 64
#define WW 64
#define HWSZ (HH*WW)          // 4096
#define COUT 128
#define KK 9

// Scratch (allocation-free per rules): __device__ globals
__device__ float g_off[BN * 4 * HWSZ];        // off channels 0..3 (ch 4 unused by reference)
__device__ float g_wk[KK * CC * COUT];        // weights transposed to [k][c][o]

__constant__ float c_by[9]     = {-1,-1,-1, 0,0,0, 1,1,1};
__constant__ float c_bx[9]     = {-1, 0, 1,-1,0,1,-1,0,1};
__constant__ float c_corner[9] = { 1, 0, 1, 0,0,0, 1,0,1};
__constant__ float c_edge[9]   = { 0, 1, 0, 1,0,1, 0,1,0};

// ---------------------------------------------------------------------------
// Kernel A: 3x3 offset conv, 4 output channels (shift_y, shift_x, s1, s2 pre-relu)
// grid = BN * (HH/4) = 128 blocks, 256 threads (4 rows x 64 cols per block)
// ---------------------------------------------------------------------------
__global__ void __launch_bounds__(256) offset_kernel(const float* __restrict__ x,
                                                     const float* __restrict__ w_off,
                                                     const float* __restrict__ b_off) {
    __shared__ float ws[4 * CC * 9];   // 18 KB; w_off layout [ch][c][3][3] flat
    int t = threadIdx.x;
    for (int i = t; i < 4 * CC * 9; i += 256) ws[i] = w_off[i];
    __syncthreads();

    int b = blockIdx.x >> 4;
    int h = ((blockIdx.x & 15) << 2) + (t >> 6);
    int w = t & 63;

    const float* xb = x + (size_t)b * CC * HWSZ;
    float a0 = b_off[0], a1 = b_off[1], a2 = b_off[2], a3 = b_off[3];

    for (int c = 0; c < CC; ++c) {
        const float* xc = xb + c * HWSZ;
        float v[9];
        #pragma unroll
        for (int dy = -1; dy <= 1; ++dy) {
            int y = h + dy;
            bool vy = ((unsigned)y < (unsigned)HH);
            #pragma unroll
            for (int dx = -1; dx <= 1; ++dx) {
                int xx = w + dx;
                int kidx = (dy + 1) * 3 + (dx + 1);
                v[kidx] = (vy && ((unsigned)xx < (unsigned)WW)) ? xc[y * WW + xx] : 0.0f;
            }
        }
        const float* wc = ws + c * 9;
        #pragma unroll
        for (int kidx = 0; kidx < 9; ++kidx) {
            a0 = fmaf(v[kidx], wc[kidx],               a0);
            a1 = fmaf(v[kidx], wc[1152 + kidx],        a1);
            a2 = fmaf(v[kidx], wc[2304 + kidx],        a2);
            a3 = fmaf(v[kidx], wc[3456 + kidx],        a3);
        }
    }

    float* ob = g_off + (size_t)b * 4 * HWSZ;
    int p = h * WW + w;
    ob[p]            = a0;
    ob[HWSZ + p]     = a1;
    ob[2*HWSZ + p]   = a2;
    ob[3*HWSZ + p]   = a3;
}

// ---------------------------------------------------------------------------
// Kernel B: transpose w[o][c][k] -> g_wk[k][c][o]
// ---------------------------------------------------------------------------
__global__ void wtrans_kernel(const float* __restrict__ w) {
    int i = blockIdx.x * 256 + threadIdx.x;
    if (i < COUT * CC * KK) {
        int o = i / (CC * KK);
        int rem = i - o * (CC * KK);
        int c = rem / KK;
        int k = rem - c * KK;
        g_wk[(k * CC + c) * COUT + o] = w[i];
    }
}

// ---------------------------------------------------------------------------
// Kernel C: deformable gather + implicit GEMM
// grid = BN*HH = 512 blocks (one per (b, h-row): 64 pixels x 128 cout)
// 256 threads. Dyn smem: Wsm[128c][128o] (64KB) + S[128c][64pix] (32KB)
// Register tile: each thread 4 o x 8 pix.
// ---------------------------------------------------------------------------
__global__ void __launch_bounds__(256, 2) deform_kernel(const float* __restrict__ x,
                                                        const float* __restrict__ bias,
                                                        float* __restrict__ out) {
    extern __shared__ float sm[];
    float* Wsm = sm;                 // 16384 floats
    float* Ssm = sm + CC * COUT;     // 8192 floats

    int t = threadIdx.x;
    int b = blockIdx.x >> 6;
    int h = blockIdx.x & 63;

    // ---- fill-role identity: one pixel per thread, 32 c's each (c = fc0 + 4*j)
    int fpix = t & 63;
    int fc0  = t >> 6;     // 0..3
    const float* offb = g_off + (size_t)b * 4 * HWSZ;
    int p = h * WW + fpix;
    float sy  = offb[p];
    float sx  = offb[HWSZ + p];
    float sc1 = fmaxf(offb[2*HWSZ + p], 0.0f) + 1.0f;
    float sc2 = fmaxf(offb[3*HWSZ + p], 0.0f) + 1.0f;

    // ---- compute-role identity
    int to4 = (t >> 3) << 2;   // o base (0,4,...,124)
    int tp8 = (t & 7) << 3;    // pix base (0,8,...,56)

    float acc[4][8];
    #pragma unroll
    for (int oi = 0; oi < 4; ++oi)
        #pragma unroll
        for (int pj = 0; pj < 8; ++pj) acc[oi][pj] = 0.0f;

    const float* xb = x + (size_t)b * CC * HWSZ;

    for (int kk = 0; kk < 9; ++kk) {
        __syncthreads();  // previous iteration's compute done before refilling smem

        // cooperative load of W[kk] slice (contiguous, L2-resident)
        {
            const float4* src = (const float4*)(g_wk + kk * CC * COUT);
            float4* dst = (float4*)Wsm;
            #pragma unroll
            for (int i = 0; i < 16; ++i) dst[t + 256 * i] = src[t + 256 * i];
        }

        // per-pixel sampling coords for this k
        float sck = c_corner[kk] * sc1 + c_edge[kk] * sc2;
        float py = (float)h    + c_by[kk] * sck + sy;
        float px = (float)fpix + c_bx[kk] * sck + sx;
        float y0f = floorf(py), x0f = floorf(px);
        float wy = py - y0f, wx = px - x0f;
        int y0 = (int)y0f, x0 = (int)x0f;
        int y1 = y0 + 1,   x1 = x0 + 1;
        float w00 = (1.0f - wy) * (1.0f - wx);
        float w01 = (1.0f - wy) * wx;
        float w10 = wy * (1.0f - wx);
        float w11 = wy * wx;
        bool vy0 = ((unsigned)y0 < (unsigned)HH), vy1 = ((unsigned)y1 < (unsigned)HH);
        bool vx0 = ((unsigned)x0 < (unsigned)WW), vx1 = ((unsigned)x1 < (unsigned)WW);
        if (!(vy0 && vx0)) w00 = 0.0f;
        if (!(vy0 && vx1)) w01 = 0.0f;
        if (!(vy1 && vx0)) w10 = 0.0f;
        if (!(vy1 && vx1)) w11 = 0.0f;
        int y0c = min(max(y0, 0), HH - 1), y1c = min(max(y1, 0), HH - 1);
        int x0c = min(max(x0, 0), WW - 1), x1c = min(max(x1, 0), WW - 1);
        int i00 = y0c * WW + x0c, i01 = y0c * WW + x1c;
        int i10 = y1c * WW + x0c, i11 = y1c * WW + x1c;

        // bilinear gather into S[c][pix]
        #pragma unroll 8
        for (int j = 0; j < 32; ++j) {
            int c = fc0 + (j << 2);
            const float* xc = xb + c * HWSZ;
            float v = w00 * xc[i00] + w01 * xc[i01] + w10 * xc[i10] + w11 * xc[i11];
            Ssm[(c << 6) + fpix] = v;
        }

        __syncthreads();

        // GEMM accumulate: 4 o x 8 pix per thread over 128 c
        #pragma unroll 2
        for (int c = 0; c < CC; ++c) {
            float4 wv = *(const float4*)(Wsm + (c << 7) + to4);
            float4 s0 = *(const float4*)(Ssm + (c << 6) + tp8);
            float4 s1 = *(const float4*)(Ssm + (c << 6) + tp8 + 4);
            float sv[8] = {s0.x, s0.y, s0.z, s0.w, s1.x, s1.y, s1.z, s1.w};
            float wvv[4] = {wv.x, wv.y, wv.z, wv.w};
            #pragma unroll
            for (int oi = 0; oi < 4; ++oi)
                #pragma unroll
                for (int pj = 0; pj < 8; ++pj)
                    acc[oi][pj] = fmaf(wvv[oi], sv[pj], acc[oi][pj]);
        }
    }

    // epilogue: bias + store (float4, coalesced per o row)
    #pragma unroll
    for (int oi = 0; oi < 4; ++oi) {
        float bb = bias[to4 + oi];
        float4 r0 = make_float4(acc[oi][0] + bb, acc[oi][1] + bb, acc[oi][2] + bb, acc[oi][3] + bb);
        float4 r1 = make_float4(acc[oi][4] + bb, acc[oi][5] + bb, acc[oi][6] + bb, acc[oi][7] + bb);
        float4* op = (float4*)(out + ((size_t)b * COUT + to4 + oi) * HWSZ + h * WW + tp8);
        op[0] = r0;
        op[1] = r1;
    }
}

// ---------------------------------------------------------------------------
extern "C" void kernel_launch(void* const* d_in, const int* in_sizes, int n_in,
                              void* d_out, int out_size) {
    const float* x     = (const float*)d_in[0];
    const float* w_off = (const float*)d_in[1];
    const float* b_off = (const float*)d_in[2];
    const float* w     = (const float*)d_in[3];
    const float* bias  = (const float*)d_in[4];
    float* out = (float*)d_out;

    cudaFuncSetAttribute(deform_kernel, cudaFuncAttributeMaxDynamicSharedMemorySize, 98304);

    offset_kernel<<<BN * (HH / 4), 256>>>(x, w_off, b_off);
    wtrans_kernel<<<(COUT * CC * KK + 255) / 256, 256>>>(w);
    deform_kernel<<<BN * HH, 256, 98304>>>(x, bias, out);
}

// round 6
// speedup vs baseline: 2.0545x; 2.0545x over previous
#include <cuda_runtime.h>
#include <cuda_bf16.h>
#include <cstdint>
#include <math.h>

#define BN 8
#define CC 128
#define HH 64
#define WW 64
#define HWSZ 4096
#define COUT 128

// ---------------- scratch (__device__ globals; no allocs allowed) ----------
__device__ float g_xT[BN * HWSZ * CC];         // NHWC transpose of x (16MB)
__device__ float g_off[BN * 4 * HWSZ];         // offset conv outputs (raw)
__device__ __nv_bfloat16 g_wb[9 * 2 * 16384];  // per-tap B tiles [k][hi|lo][128k x 128n bf16, swizzled]
__device__ float g_woff[9 * CC * 4];           // offset weights [k][c][ch]

__constant__ float c_by[9]     = {-1,-1,-1, 0,0,0, 1,1,1};
__constant__ float c_bx[9]     = {-1, 0, 1,-1,0,1,-1,0,1};
__constant__ float c_corner[9] = { 1, 0, 1, 0,0,0, 1,0,1};
__constant__ float c_edge[9]   = { 0, 1, 0, 1,0,1, 0,1,0};

__device__ __forceinline__ uint32_t smem_to_u32(const void* p) {
    uint32_t a;
    asm("{ .reg .u64 t; cvta.to.shared.u64 t, %1; cvt.u32.u64 %0, t; }" : "=r"(a) : "l"(p));
    return a;
}

// Tile layout: row-major, 128 bf16 (256 B) per row, 16B cells xor-swizzled by (row&7).
// byte(row, bytecol) = row*256 + (((bytecol>>4) ^ (row&7))<<4) + (bytecol&15)
__device__ __forceinline__ uint32_t tile_byte(int row, int bytecol) {
    return (uint32_t)row * 256u + ((((uint32_t)bytecol >> 4) ^ ((uint32_t)row & 7u)) << 4) + ((uint32_t)bytecol & 15u);
}

// ---------------------------------------------------------------------------
// K1: NCHW -> NHWC transpose of x into g_xT
// ---------------------------------------------------------------------------
__global__ void __launch_bounds__(256) transpose_kernel(const float* __restrict__ x) {
    __shared__ float tile[32 * 129];
    int t = threadIdx.x;
    int b = blockIdx.x >> 7;
    int hw0 = (blockIdx.x & 127) << 5;
    const float* xb = x + (size_t)b * CC * HWSZ;
    #pragma unroll
    for (int cc = 0; cc < 16; ++cc) {
        int c = cc * 8 + (t >> 5);
        tile[(t & 31) * 129 + c] = xb[(size_t)c * HWSZ + hw0 + (t & 31)];
    }
    __syncthreads();
    float* dst = g_xT + ((size_t)b * HWSZ + hw0) * CC;
    #pragma unroll
    for (int i = 0; i < 16; ++i) {
        int idx = t + 256 * i;
        dst[idx] = tile[(idx >> 7) * 129 + (idx & 127)];
    }
}

// ---------------------------------------------------------------------------
// K2: main weights -> bf16 hi/lo tiles [k][hi|lo][K=c rows x N=o cols], swizzled
// ---------------------------------------------------------------------------
__global__ void wprep_kernel(const float* __restrict__ w) {
    int i = blockIdx.x * 256 + threadIdx.x;
    if (i >= COUT * CC * 9) return;
    int o = i / 1152;
    int rem = i - o * 1152;
    int c = rem / 9;
    int k = rem - c * 9;
    float v = w[i];
    __nv_bfloat16 hi = __float2bfloat16(v);
    __nv_bfloat16 lo = __float2bfloat16(v - __bfloat162float(hi));
    uint32_t off = tile_byte(c, o * 2) >> 1;
    g_wb[k * 32768 + off] = hi;
    g_wb[k * 32768 + 16384 + off] = lo;
}

// K2b: offset weights [ch][c][3][3] -> [k][c][ch]
__global__ void woffprep_kernel(const float* __restrict__ w_off) {
    int i = blockIdx.x * 256 + threadIdx.x;   // 9*128*4 = 4608
    if (i >= 4608) return;
    int k = i >> 9;
    int r = i & 511;
    int c = r >> 2;
    int ch = r & 3;
    g_woff[i] = w_off[(ch * CC + c) * 9 + k];
}

// ---------------------------------------------------------------------------
// K3: offset conv, warp-per-pixel on NHWC, shfl reduce
// ---------------------------------------------------------------------------
__global__ void __launch_bounds__(256) offset_kernel(const float* __restrict__ b_off) {
    int gw = (blockIdx.x * 256 + threadIdx.x) >> 5;
    int lane = threadIdx.x & 31;
    int b = gw >> 12;
    int hw = gw & 4095;
    int h = hw >> 6, wv = hw & 63;
    float a0 = 0.f, a1 = 0.f, a2 = 0.f, a3 = 0.f;
    const float* xTb = g_xT + (size_t)b * HWSZ * CC;
    #pragma unroll
    for (int k = 0; k < 9; ++k) {
        int ty = h + k / 3 - 1, tx = wv + k % 3 - 1;
        if ((unsigned)ty < 64u && (unsigned)tx < 64u) {
            const float* row = xTb + (ty * 64 + tx) * CC;
            #pragma unroll
            for (int j = 0; j < 4; ++j) {
                int c = lane + 32 * j;
                float xv = row[c];
                float4 wv4 = *(const float4*)(g_woff + (k * CC + c) * 4);
                a0 = fmaf(xv, wv4.x, a0);
                a1 = fmaf(xv, wv4.y, a1);
                a2 = fmaf(xv, wv4.z, a2);
                a3 = fmaf(xv, wv4.w, a3);
            }
        }
    }
    #pragma unroll
    for (int s = 16; s; s >>= 1) {
        a0 += __shfl_xor_sync(0xffffffffu, a0, s);
        a1 += __shfl_xor_sync(0xffffffffu, a1, s);
        a2 += __shfl_xor_sync(0xffffffffu, a2, s);
        a3 += __shfl_xor_sync(0xffffffffu, a3, s);
    }
    if (lane == 0) {
        float* ob = g_off + (size_t)b * 4 * HWSZ;
        ob[hw]          = a0 + b_off[0];
        ob[4096 + hw]   = a1 + b_off[1];
        ob[8192 + hw]   = a2 + b_off[2];
        ob[12288 + hw]  = a3 + b_off[3];
    }
}

// ---------------------------------------------------------------------------
// K4: deformable gather + mma.sync bf16-split implicit GEMM
// grid = BN*HH = 512 blocks; block = (b, h row): M=64 pixels x N=128 cout.
// 8 warps: warp (wr = wid>>1) rows 16*wr..+15, (wc = wid&1) cols 64*wc..+63.
// SMEM: Ahi 16K | Alo 16K | Bhi 32K | Blo 32K | soff 1K | bias 0.5K
// ---------------------------------------------------------------------------
#define SM_AHI 0
#define SM_ALO 16384
#define SM_BHI 32768
#define SM_BLO 65536
#define SM_SOFF 98304
#define SM_BIAS 99328
#define SM_TOTAL 99840

__global__ void __launch_bounds__(256, 2)
deform_mma_kernel(const float* __restrict__ bias, float* __restrict__ out) {
    extern __shared__ __align__(1024) char smem[];
    uint32_t smem_base = smem_to_u32(smem);
    float* soff = (float*)(smem + SM_SOFF);
    float* bias_sm = (float*)(smem + SM_BIAS);

    int t = threadIdx.x;
    int wid = t >> 5;
    int lane = t & 31;
    int b = blockIdx.x >> 6;
    int h = blockIdx.x & 63;

    // per-pixel sampling params
    const float* offb = g_off + (size_t)b * 4 * HWSZ;
    if (t < 64) {
        int hw = h * 64 + t;
        soff[t]       = offb[hw];
        soff[64 + t]  = offb[4096 + hw];
        soff[128 + t] = fmaxf(offb[8192 + hw], 0.f) + 1.f;
        soff[192 + t] = fmaxf(offb[12288 + hw], 0.f) + 1.f;
    }
    if (t < 128) bias_sm[t] = bias[t];

    float acc[8][4];
    #pragma unroll
    for (int i = 0; i < 8; ++i)
        #pragma unroll
        for (int j = 0; j < 4; ++j) acc[i][j] = 0.f;

    const float* xTb = g_xT + (size_t)b * HWSZ * CC;
    int m0 = (wid >> 1) << 4;
    int n0 = (wid & 1) << 6;

    // precomputed ldmatrix thread addresses (row/col parts)
    int lrow = lane & 15;                 // row within 16-row tile
    int lcol16 = (lane >> 4) << 4;        // +0 or +16 bytes

    for (int k = 0; k < 9; ++k) {
        __syncthreads();   // previous tap's MMAs done before refilling smem

        // ---- B tiles: copy 64KB (hi+lo) for this tap
        {
            const float4* src = (const float4*)(g_wb + k * 32768);
            float4* dst = (float4*)(smem + SM_BHI);
            #pragma unroll
            for (int i = 0; i < 16; ++i) dst[t + 256 * i] = src[t + 256 * i];
        }

        // ---- gather: warp wid fills pixels 8*wid..+7; lane covers c=4*lane..+3
        float byk = c_by[k], bxk = c_bx[k], ck = c_corner[k], ek = c_edge[k];
        #pragma unroll
        for (int pp = 0; pp < 8; ++pp) {
            int r = (wid << 3) + pp;
            float sy = soff[r], sx = soff[64 + r], s1 = soff[128 + r], s2 = soff[192 + r];
            float sck = ck * s1 + ek * s2;
            float py = (float)h        + byk * sck + sy;
            float px = (float)r        + bxk * sck + sx;
            float y0f = floorf(py), x0f = floorf(px);
            float wy = py - y0f, wx = px - x0f;
            int y0 = (int)y0f, x0 = (int)x0f, y1 = y0 + 1, x1 = x0 + 1;
            float w00 = (1.f - wy) * (1.f - wx);
            float w01 = (1.f - wy) * wx;
            float w10 = wy * (1.f - wx);
            float w11 = wy * wx;
            if (!(((unsigned)y0 < 64u) && ((unsigned)x0 < 64u))) w00 = 0.f;
            if (!(((unsigned)y0 < 64u) && ((unsigned)x1 < 64u))) w01 = 0.f;
            if (!(((unsigned)y1 < 64u) && ((unsigned)x0 < 64u))) w10 = 0.f;
            if (!(((unsigned)y1 < 64u) && ((unsigned)x1 < 64u))) w11 = 0.f;
            int y0c = min(max(y0, 0), 63), y1c = min(max(y1, 0), 63);
            int x0c = min(max(x0, 0), 63), x1c = min(max(x1, 0), 63);
            int i00 = y0c * 64 + x0c, i01 = y0c * 64 + x1c;
            int i10 = y1c * 64 + x0c, i11 = y1c * 64 + x1c;

            float4 v00 = ((const float4*)(xTb + (size_t)i00 * CC))[lane];
            float4 v01 = ((const float4*)(xTb + (size_t)i01 * CC))[lane];
            float4 v10 = ((const float4*)(xTb + (size_t)i10 * CC))[lane];
            float4 v11 = ((const float4*)(xTb + (size_t)i11 * CC))[lane];
            float4 v;
            v.x = fmaf(w11, v11.x, fmaf(w10, v10.x, fmaf(w01, v01.x, w00 * v00.x)));
            v.y = fmaf(w11, v11.y, fmaf(w10, v10.y, fmaf(w01, v01.y, w00 * v00.y)));
            v.z = fmaf(w11, v11.z, fmaf(w10, v10.z, fmaf(w01, v01.z, w00 * v00.z)));
            v.w = fmaf(w11, v11.w, fmaf(w10, v10.w, fmaf(w01, v01.w, w00 * v00.w)));

            __nv_bfloat16 h0b = __float2bfloat16(v.x);
            __nv_bfloat16 h1b = __float2bfloat16(v.y);
            __nv_bfloat16 h2b = __float2bfloat16(v.z);
            __nv_bfloat16 h3b = __float2bfloat16(v.w);
            __nv_bfloat16 l0b = __float2bfloat16(v.x - __bfloat162float(h0b));
            __nv_bfloat16 l1b = __float2bfloat16(v.y - __bfloat162float(h1b));
            __nv_bfloat16 l2b = __float2bfloat16(v.z - __bfloat162float(h2b));
            __nv_bfloat16 l3b = __float2bfloat16(v.w - __bfloat162float(h3b));
            __nv_bfloat162 hp0, hp1, lp0, lp1;
            hp0.x = h0b; hp0.y = h1b; hp1.x = h2b; hp1.y = h3b;
            lp0.x = l0b; lp0.y = l1b; lp1.x = l2b; lp1.y = l3b;

            // bytecol = 8*lane; swizzled cell write (8B within a 16B cell)
            uint32_t off = (uint32_t)r * 256u + ((((uint32_t)lane >> 1) ^ ((uint32_t)r & 7u)) << 4) + ((lane & 1) << 3);
            *(uint2*)(smem + SM_AHI + off) = make_uint2(*(uint32_t*)&hp0, *(uint32_t*)&hp1);
            *(uint2*)(smem + SM_ALO + off) = make_uint2(*(uint32_t*)&lp0, *(uint32_t*)&lp1);
        }

        __syncthreads();

        // ---- 3 compensated passes: (Ahi,Bhi), (Alo,Bhi), (Ahi,Blo)
        #pragma unroll
        for (int pass = 0; pass < 3; ++pass) {
            uint32_t aBase = smem_base + (pass == 1 ? SM_ALO : SM_AHI);
            uint32_t bBase = smem_base + (pass == 2 ? SM_BLO : SM_BHI);
            #pragma unroll
            for (int kb = 0; kb < 8; ++kb) {
                int k0 = kb << 4;
                // A frag: 16x16 at (m0, k0)
                int arow = m0 + lrow;
                uint32_t aaddr = aBase + tile_byte(arow, k0 * 2 + lcol16);
                uint32_t a0, a1, a2, a3;
                asm volatile("ldmatrix.sync.aligned.m8n8.x4.shared.b16 {%0,%1,%2,%3}, [%4];"
                             : "=r"(a0), "=r"(a1), "=r"(a2), "=r"(a3) : "r"(aaddr));
                int brow = k0 + lrow;
                #pragma unroll
                for (int nb = 0; nb < 4; ++nb) {
                    uint32_t baddr = bBase + tile_byte(brow, (n0 + nb * 16) * 2 + lcol16);
                    uint32_t b0, b1, b2, b3;
                    asm volatile("ldmatrix.sync.aligned.m8n8.x4.trans.shared.b16 {%0,%1,%2,%3}, [%4];"
                                 : "=r"(b0), "=r"(b1), "=r"(b2), "=r"(b3) : "r"(baddr));
                    float* c0 = acc[nb * 2];
                    float* c1 = acc[nb * 2 + 1];
                    asm volatile("mma.sync.aligned.m16n8k16.row.col.f32.bf16.bf16.f32 "
                                 "{%0,%1,%2,%3}, {%4,%5,%6,%7}, {%8,%9}, {%0,%1,%2,%3};"
                                 : "+f"(c0[0]), "+f"(c0[1]), "+f"(c0[2]), "+f"(c0[3])
                                 : "r"(a0), "r"(a1), "r"(a2), "r"(a3), "r"(b0), "r"(b1));
                    asm volatile("mma.sync.aligned.m16n8k16.row.col.f32.bf16.bf16.f32 "
                                 "{%0,%1,%2,%3}, {%4,%5,%6,%7}, {%8,%9}, {%0,%1,%2,%3};"
                                 : "+f"(c1[0]), "+f"(c1[1]), "+f"(c1[2]), "+f"(c1[3])
                                 : "r"(a0), "r"(a1), "r"(a2), "r"(a3), "r"(b2), "r"(b3));
                }
            }
        }
    }

    // ---- epilogue: bias + store (NCHW out)
    int r0 = m0 + (lane >> 2);
    float* outb = out + (size_t)b * COUT * HWSZ + h * 64;
    #pragma unroll
    for (int nb = 0; nb < 8; ++nb) {
        int o = n0 + nb * 8 + ((lane & 3) << 1);
        float bb0 = bias_sm[o], bb1 = bias_sm[o + 1];
        outb[(size_t)o * HWSZ + r0]            = acc[nb][0] + bb0;
        outb[(size_t)(o + 1) * HWSZ + r0]      = acc[nb][1] + bb1;
        outb[(size_t)o * HWSZ + r0 + 8]        = acc[nb][2] + bb0;
        outb[(size_t)(o + 1) * HWSZ + r0 + 8]  = acc[nb][3] + bb1;
    }
}

// ---------------------------------------------------------------------------
extern "C" void kernel_launch(void* const* d_in, const int* in_sizes, int n_in,
                              void* d_out, int out_size) {
    const float* x     = (const float*)d_in[0];
    const float* w_off = (const float*)d_in[1];
    const float* b_off = (const float*)d_in[2];
    const float* w     = (const float*)d_in[3];
    const float* bias  = (const float*)d_in[4];
    float* out = (float*)d_out;

    cudaFuncSetAttribute(deform_mma_kernel, cudaFuncAttributeMaxDynamicSharedMemorySize, SM_TOTAL);

    transpose_kernel<<<BN * 128, 256>>>(x);
    wprep_kernel<<<(COUT * CC * 9 + 255) / 256, 256>>>(w);
    woffprep_kernel<<<18, 256>>>(w_off);
    offset_kernel<<<4096, 256>>>(b_off);
    deform_mma_kernel<<<BN * HH, 256, SM_TOTAL>>>(bias, out);
}

// round 11
// speedup vs baseline: 3.3860x; 1.6481x over previous
#include <cuda_runtime.h>
#include <cuda_bf16.h>
#include <cstdint>
#include <math.h>

#define BN 8
#define CC 128
#define HH 64
#define WW 64
#define HWSZ 4096
#define COUT 128

// ---------------- scratch (__device__ globals; no allocs allowed) ----------
__device__ float g_xT[BN * HWSZ * CC];         // NHWC transpose of x (16MB)
__device__ float g_off[BN * 4 * HWSZ];         // offset conv outputs (raw)
__device__ __nv_bfloat16 g_wb[9 * 2 * 16384];  // per-tap B tiles [k][hi|lo][128k x 128n bf16, swizzled]
__device__ float g_woff[9 * 4 * CC];           // offset weights [k][ch][c]

__constant__ float c_by[9]     = {-1,-1,-1, 0,0,0, 1,1,1};
__constant__ float c_bx[9]     = {-1, 0, 1,-1,0,1,-1,0,1};
__constant__ float c_corner[9] = { 1, 0, 1, 0,0,0, 1,0,1};
__constant__ float c_edge[9]   = { 0, 1, 0, 1,0,1, 0,1,0};

__device__ __forceinline__ uint32_t smem_to_u32(const void* p) {
    uint32_t a;
    asm("{ .reg .u64 t; cvta.to.shared.u64 t, %1; cvt.u32.u64 %0, t; }" : "=r"(a) : "l"(p));
    return a;
}

// Tile layout: row-major, 128 bf16 (256 B) per row, 16B cells xor-swizzled by (row&7).
__device__ __forceinline__ uint32_t tile_byte(int row, int bytecol) {
    return (uint32_t)row * 256u + ((((uint32_t)bytecol >> 4) ^ ((uint32_t)row & 7u)) << 4) + ((uint32_t)bytecol & 15u);
}

// ---------------------------------------------------------------------------
// K1: NCHW -> NHWC transpose of x into g_xT
// ---------------------------------------------------------------------------
__global__ void __launch_bounds__(256) transpose_kernel(const float* __restrict__ x) {
    __shared__ float tile[32 * 129];
    int t = threadIdx.x;
    int b = blockIdx.x >> 7;
    int hw0 = (blockIdx.x & 127) << 5;
    const float* xb = x + (size_t)b * CC * HWSZ;
    #pragma unroll
    for (int cc = 0; cc < 16; ++cc) {
        int c = cc * 8 + (t >> 5);
        tile[(t & 31) * 129 + c] = xb[(size_t)c * HWSZ + hw0 + (t & 31)];
    }
    __syncthreads();
    float* dst = g_xT + ((size_t)b * HWSZ + hw0) * CC;
    #pragma unroll
    for (int i = 0; i < 16; ++i) {
        int idx = t + 256 * i;
        dst[idx] = tile[(idx >> 7) * 129 + (idx & 127)];
    }
}

// ---------------------------------------------------------------------------
// K2: main weights -> bf16 hi/lo tiles [k][hi|lo][K=c rows x N=o cols], swizzled
// ---------------------------------------------------------------------------
__global__ void wprep_kernel(const float* __restrict__ w) {
    int i = blockIdx.x * 256 + threadIdx.x;
    if (i >= COUT * CC * 9) return;
    int o = i / 1152;
    int rem = i - o * 1152;
    int c = rem / 9;
    int k = rem - c * 9;
    float v = w[i];
    __nv_bfloat16 hi = __float2bfloat16(v);
    __nv_bfloat16 lo = __float2bfloat16(v - __bfloat162float(hi));
    uint32_t off = tile_byte(c, o * 2) >> 1;
    g_wb[k * 32768 + off] = hi;
    g_wb[k * 32768 + 16384 + off] = lo;
}

// K2b: offset weights [ch][c][3][3] -> [k][ch][c]
__global__ void woffprep_kernel(const float* __restrict__ w_off) {
    int i = blockIdx.x * 256 + threadIdx.x;   // 9*4*128 = 4608
    if (i >= 4608) return;
    int k = i >> 9;
    int r = i & 511;
    int ch = r >> 7;
    int c = r & 127;
    g_woff[i] = w_off[(ch * CC + c) * 9 + k];
}

// ---------------------------------------------------------------------------
// K3: offset conv — 16 px/warp, weights register-hoisted per tap.
// ---------------------------------------------------------------------------
__global__ void __launch_bounds__(256) offset_kernel(const float* __restrict__ b_off) {
    int wid = threadIdx.x >> 5, lane = threadIdx.x & 31;
    int gw = blockIdx.x * 8 + wid;
    int pix0 = gw << 4;
    int b = pix0 >> 12;
    int hw = pix0 & 4095;
    int h = hw >> 6, w0 = hw & 63;
    const float* xTb = g_xT + (size_t)b * HWSZ * CC;

    float acc[16][4];
    #pragma unroll
    for (int p = 0; p < 16; ++p)
        #pragma unroll
        for (int ch = 0; ch < 4; ++ch) acc[p][ch] = 0.f;

    #pragma unroll
    for (int k = 0; k < 9; ++k) {
        int ty = h + k / 3 - 1;
        int dxk = k % 3 - 1;
        float4 wv[4];
        #pragma unroll
        for (int ch = 0; ch < 4; ++ch)
            wv[ch] = *(const float4*)(g_woff + (k * 4 + ch) * CC + 4 * lane);
        if ((unsigned)ty < 64u) {
            const float* rowb = xTb + (size_t)ty * 64 * CC + 4 * lane;
            #pragma unroll
            for (int p = 0; p < 16; ++p) {
                int tx = w0 + p + dxk;
                if ((unsigned)tx < 64u) {
                    float4 xv = *(const float4*)(rowb + tx * CC);
                    #pragma unroll
                    for (int ch = 0; ch < 4; ++ch)
                        acc[p][ch] = fmaf(xv.x, wv[ch].x, fmaf(xv.y, wv[ch].y,
                                     fmaf(xv.z, wv[ch].z, fmaf(xv.w, wv[ch].w, acc[p][ch]))));
                }
            }
        }
    }

    float bb0 = b_off[0], bb1 = b_off[1], bb2 = b_off[2], bb3 = b_off[3];
    float* ob = g_off + (size_t)b * 4 * HWSZ;
    #pragma unroll
    for (int p = 0; p < 16; ++p) {
        float a0 = acc[p][0], a1 = acc[p][1], a2 = acc[p][2], a3 = acc[p][3];
        #pragma unroll
        for (int s = 16; s; s >>= 1) {
            a0 += __shfl_xor_sync(0xffffffffu, a0, s);
            a1 += __shfl_xor_sync(0xffffffffu, a1, s);
            a2 += __shfl_xor_sync(0xffffffffu, a2, s);
            a3 += __shfl_xor_sync(0xffffffffu, a3, s);
        }
        if (lane == 0) {
            int pw = hw + p;
            ob[pw]          = a0 + bb0;
            ob[4096 + pw]   = a1 + bb1;
            ob[8192 + pw]   = a2 + bb2;
            ob[12288 + pw]  = a3 + bb3;
        }
    }
}

// ---------------------------------------------------------------------------
// K4: deformable gather + fused 3-term bf16 MMA, M=128/block, cp.async B pipeline
// ---------------------------------------------------------------------------
#define SM_AHI 0
#define SM_ALO 32768
#define SM_B0  65536
#define SM_B1  131072
#define SM_SOFF 196608
#define SM_BIAS 198656
#define SM_TOTAL 199168

__device__ __forceinline__ void issue_b_copy(int k, uint32_t dst_smem, int t) {
    const char* src = (const char*)(g_wb + (size_t)k * 32768);
    #pragma unroll
    for (int i = 0; i < 8; ++i) {
        uint32_t o = (uint32_t)(t + i * 512) * 16u;
        asm volatile("cp.async.cg.shared.global [%0], [%1], 16;"
                     :: "r"(dst_smem + o), "l"(src + o) : "memory");
    }
    asm volatile("cp.async.commit_group;" ::: "memory");
}

__global__ void __launch_bounds__(512, 1)
deform_mma_kernel(const float* __restrict__ bias, float* __restrict__ out) {
    extern __shared__ __align__(1024) char smem[];
    uint32_t smem_base = smem_to_u32(smem);
    float* soff = (float*)(smem + SM_SOFF);
    float* bias_sm = (float*)(smem + SM_BIAS);

    int t = threadIdx.x;
    int wid = t >> 5;
    int lane = t & 31;
    int b = blockIdx.x >> 5;
    int h0 = (blockIdx.x & 31) << 1;

    const float* offb = g_off + (size_t)b * 4 * HWSZ;
    if (t < 128) {
        int hw = h0 * 64 + t;
        soff[t]       = offb[hw];
        soff[128 + t] = offb[4096 + hw];
        soff[256 + t] = fmaxf(offb[8192 + hw], 0.f) + 1.f;
        soff[384 + t] = fmaxf(offb[12288 + hw], 0.f) + 1.f;
        bias_sm[t] = bias[t];
    }

    issue_b_copy(0, smem_base + SM_B0, t);

    float acc[2][4][4];
    #pragma unroll
    for (int i = 0; i < 2; ++i)
        #pragma unroll
        for (int j = 0; j < 4; ++j)
            #pragma unroll
            for (int l = 0; l < 4; ++l) acc[i][j][l] = 0.f;

    const float* xTb = g_xT + (size_t)b * HWSZ * CC;
    int m0 = (wid >> 2) << 5;
    int n0 = (wid & 3) << 5;
    int lrow = lane & 15;
    int lcol16 = (lane >> 4) << 4;

    for (int k = 0; k < 9; ++k) {
        __syncthreads();

        if (k < 8) issue_b_copy(k + 1, smem_base + ((k & 1) ? SM_B0 : SM_B1), t);

        float byk = c_by[k], bxk = c_bx[k], ck = c_corner[k], ek = c_edge[k];
        #pragma unroll
        for (int pp = 0; pp < 8; ++pp) {
            int r = (wid << 3) + pp;
            float sy = soff[r], sx = soff[128 + r], s1 = soff[256 + r], s2 = soff[384 + r];
            float sck = ck * s1 + ek * s2;
            float py = (float)(h0 + (r >> 6)) + byk * sck + sy;
            float px = (float)(r & 63)        + bxk * sck + sx;
            float y0f = floorf(py), x0f = floorf(px);
            float wy = py - y0f, wx = px - x0f;
            int y0 = (int)y0f, x0 = (int)x0f, y1 = y0 + 1, x1 = x0 + 1;
            float w00 = (1.f - wy) * (1.f - wx);
            float w01 = (1.f - wy) * wx;
            float w10 = wy * (1.f - wx);
            float w11 = wy * wx;
            if (!(((unsigned)y0 < 64u) && ((unsigned)x0 < 64u))) w00 = 0.f;
            if (!(((unsigned)y0 < 64u) && ((unsigned)x1 < 64u))) w01 = 0.f;
            if (!(((unsigned)y1 < 64u) && ((unsigned)x0 < 64u))) w10 = 0.f;
            if (!(((unsigned)y1 < 64u) && ((unsigned)x1 < 64u))) w11 = 0.f;
            int y0c = min(max(y0, 0), 63), y1c = min(max(y1, 0), 63);
            int x0c = min(max(x0, 0), 63), x1c = min(max(x1, 0), 63);
            int i00 = y0c * 64 + x0c, i01 = y0c * 64 + x1c;
            int i10 = y1c * 64 + x0c, i11 = y1c * 64 + x1c;

            float4 v00 = ((const float4*)(xTb + (size_t)i00 * CC))[lane];
            float4 v01 = ((const float4*)(xTb + (size_t)i01 * CC))[lane];
            float4 v10 = ((const float4*)(xTb + (size_t)i10 * CC))[lane];
            float4 v11 = ((const float4*)(xTb + (size_t)i11 * CC))[lane];
            float4 v;
            v.x = fmaf(w11, v11.x, fmaf(w10, v10.x, fmaf(w01, v01.x, w00 * v00.x)));
            v.y = fmaf(w11, v11.y, fmaf(w10, v10.y, fmaf(w01, v01.y, w00 * v00.y)));
            v.z = fmaf(w11, v11.z, fmaf(w10, v10.z, fmaf(w01, v01.z, w00 * v00.z)));
            v.w = fmaf(w11, v11.w, fmaf(w10, v10.w, fmaf(w01, v01.w, w00 * v00.w)));

            __nv_bfloat16 h0b = __float2bfloat16(v.x);
            __nv_bfloat16 h1b = __float2bfloat16(v.y);
            __nv_bfloat16 h2b = __float2bfloat16(v.z);
            __nv_bfloat16 h3b = __float2bfloat16(v.w);
            __nv_bfloat16 l0b = __float2bfloat16(v.x - __bfloat162float(h0b));
            __nv_bfloat16 l1b = __float2bfloat16(v.y - __bfloat162float(h1b));
            __nv_bfloat16 l2b = __float2bfloat16(v.z - __bfloat162float(h2b));
            __nv_bfloat16 l3b = __float2bfloat16(v.w - __bfloat162float(h3b));
            __nv_bfloat162 hp0, hp1, lp0, lp1;
            hp0.x = h0b; hp0.y = h1b; hp1.x = h2b; hp1.y = h3b;
            lp0.x = l0b; lp0.y = l1b; lp1.x = l2b; lp1.y = l3b;

            uint32_t off = (uint32_t)r * 256u + ((((uint32_t)lane >> 1) ^ ((uint32_t)r & 7u)) << 4) + ((lane & 1) << 3);
            *(uint2*)(smem + SM_AHI + off) = make_uint2(*(uint32_t*)&hp0, *(uint32_t*)&hp1);
            *(uint2*)(smem + SM_ALO + off) = make_uint2(*(uint32_t*)&lp0, *(uint32_t*)&lp1);
        }

        if (k < 8) { asm volatile("cp.async.wait_group 1;" ::: "memory"); }
        else       { asm volatile("cp.async.wait_group 0;" ::: "memory"); }
        __syncthreads();

        uint32_t bhiBase = smem_base + ((k & 1) ? SM_B1 : SM_B0);
        uint32_t bloBase = bhiBase + 32768;
        uint32_t ahiBase = smem_base + SM_AHI;
        uint32_t aloBase = smem_base + SM_ALO;

        #pragma unroll
        for (int kb = 0; kb < 8; ++kb) {
            int k0b = kb << 5;
            uint32_t ah0, ah1, ah2, ah3, ah4, ah5, ah6, ah7;
            uint32_t al0, al1, al2, al3, al4, al5, al6, al7;
            asm("ldmatrix.sync.aligned.m8n8.x4.shared.b16 {%0,%1,%2,%3}, [%4];"
                : "=r"(ah0), "=r"(ah1), "=r"(ah2), "=r"(ah3)
                : "r"(ahiBase + tile_byte(m0 + lrow, k0b + lcol16)));
            asm("ldmatrix.sync.aligned.m8n8.x4.shared.b16 {%0,%1,%2,%3}, [%4];"
                : "=r"(ah4), "=r"(ah5), "=r"(ah6), "=r"(ah7)
                : "r"(ahiBase + tile_byte(m0 + 16 + lrow, k0b + lcol16)));
            asm("ldmatrix.sync.aligned.m8n8.x4.shared.b16 {%0,%1,%2,%3}, [%4];"
                : "=r"(al0), "=r"(al1), "=r"(al2), "=r"(al3)
                : "r"(aloBase + tile_byte(m0 + lrow, k0b + lcol16)));
            asm("ldmatrix.sync.aligned.m8n8.x4.shared.b16 {%0,%1,%2,%3}, [%4];"
                : "=r"(al4), "=r"(al5), "=r"(al6), "=r"(al7)
                : "r"(aloBase + tile_byte(m0 + 16 + lrow, k0b + lcol16)));
            int brow = (kb << 4) + lrow;
            #pragma unroll
            for (int nb = 0; nb < 2; ++nb) {
                uint32_t bcol = (uint32_t)(n0 + nb * 16) * 2 + lcol16;
                uint32_t bh0, bh1, bh2, bh3, bl0, bl1, bl2, bl3;
                asm("ldmatrix.sync.aligned.m8n8.x4.trans.shared.b16 {%0,%1,%2,%3}, [%4];"
                    : "=r"(bh0), "=r"(bh1), "=r"(bh2), "=r"(bh3) : "r"(bhiBase + tile_byte(brow, bcol)));
                asm("ldmatrix.sync.aligned.m8n8.x4.trans.shared.b16 {%0,%1,%2,%3}, [%4];"
                    : "=r"(bl0), "=r"(bl1), "=r"(bl2), "=r"(bl3) : "r"(bloBase + tile_byte(brow, bcol)));

                float* c00 = acc[0][nb * 2];
                float* c10 = acc[1][nb * 2];
                float* c01 = acc[0][nb * 2 + 1];
                float* c11 = acc[1][nb * 2 + 1];
                #define MMA(C, A0, A1, A2, A3, B0, B1) \
                    asm("mma.sync.aligned.m16n8k16.row.col.f32.bf16.bf16.f32 " \
                        "{%0,%1,%2,%3}, {%4,%5,%6,%7}, {%8,%9}, {%0,%1,%2,%3};" \
                        : "+f"((C)[0]), "+f"((C)[1]), "+f"((C)[2]), "+f"((C)[3]) \
                        : "r"(A0), "r"(A1), "r"(A2), "r"(A3), "r"(B0), "r"(B1))
                MMA(c00, ah0, ah1, ah2, ah3, bh0, bh1);
                MMA(c10, ah4, ah5, ah6, ah7, bh0, bh1);
                MMA(c01, ah0, ah1, ah2, ah3, bh2, bh3);
                MMA(c11, ah4, ah5, ah6, ah7, bh2, bh3);
                MMA(c00, al0, al1, al2, al3, bh0, bh1);
                MMA(c10, al4, al5, al6, al7, bh0, bh1);
                MMA(c01, al0, al1, al2, al3, bh2, bh3);
                MMA(c11, al4, al5, al6, al7, bh2, bh3);
                MMA(c00, ah0, ah1, ah2, ah3, bl0, bl1);
                MMA(c10, ah4, ah5, ah6, ah7, bl0, bl1);
                MMA(c01, ah0, ah1, ah2, ah3, bl2, bl3);
                MMA(c11, ah4, ah5, ah6, ah7, bl2, bl3);
                #undef MMA
            }
        }
    }

    float* outb = out + (size_t)b * COUT * HWSZ + h0 * 64;
    #pragma unroll
    for (int mf = 0; mf < 2; ++mf) {
        int r0 = m0 + mf * 16 + (lane >> 2);
        #pragma unroll
        for (int nf = 0; nf < 4; ++nf) {
            int o = n0 + nf * 8 + ((lane & 3) << 1);
            float bb0 = bias_sm[o], bb1 = bias_sm[o + 1];
            float* a = acc[mf][nf];
            outb[(size_t)o * HWSZ + r0]             = a[0] + bb0;
            outb[(size_t)(o + 1) * HWSZ + r0]       = a[1] + bb1;
            outb[(size_t)o * HWSZ + r0 + 8]         = a[2] + bb0;
            outb[(size_t)(o + 1) * HWSZ + r0 + 8]   = a[3] + bb1;
        }
    }
}

// ---------------------------------------------------------------------------
extern "C" void kernel_launch(void* const* d_in, const int* in_sizes, int n_in,
                              void* d_out, int out_size) {
    const float* x     = (const float*)d_in[0];
    const float* w_off = (const float*)d_in[1];
    const float* b_off = (const float*)d_in[2];
    const float* w     = (const float*)d_in[3];
    const float* bias  = (const float*)d_in[4];
    float* out = (float*)d_out;

    cudaFuncSetAttribute(deform_mma_kernel, cudaFuncAttributeMaxDynamicSharedMemorySize, SM_TOTAL);

    transpose_kernel<<<BN * 128, 256>>>(x);
    wprep_kernel<<<(COUT * CC * 9 + 255) / 256, 256>>>(w);
    woffprep_kernel<<<18, 256>>>(w_off);
    offset_kernel<<<256, 256>>>(b_off);
    deform_mma_kernel<<<BN * 32, 512, SM_TOTAL>>>(bias, out);
}